// round 3
// baseline (speedup 1.0000x reference)
#include <cuda_runtime.h>
#include <stdint.h>

#define BB 512
#define SS 1024
#define TT 48

__device__ float g_partial[BB];

__device__ __forceinline__ unsigned long long pk2(float x, float y) {
    unsigned long long r;
    asm("mov.b64 %0, {%1,%2};" : "=l"(r) : "f"(x), "f"(y));
    return r;
}
__device__ __forceinline__ void upk2(unsigned long long v, float& x, float& y) {
    asm("mov.b64 {%0,%1}, %2;" : "=f"(x), "=f"(y) : "l"(v));
}
__device__ __forceinline__ unsigned long long fma2(unsigned long long a, unsigned long long b, unsigned long long c) {
    unsigned long long d;
    asm("fma.rn.f32x2 %0, %1, %2, %3;" : "=l"(d) : "l"(a), "l"(b), "l"(c));
    return d;
}
__device__ __forceinline__ unsigned long long add2(unsigned long long a, unsigned long long b) {
    unsigned long long d;
    asm("add.rn.f32x2 %0, %1, %2;" : "=l"(d) : "l"(a), "l"(b));
    return d;
}

// One warp per batch element. 4 warps per block (one per SMSP), 128 blocks.
__global__ __launch_bounds__(128, 1) void crf_main(
    const float* __restrict__ em,          // [B,S,T]
    const int* __restrict__ tags,          // [B,S]
    const unsigned char* __restrict__ mask,// [B,S] bool OR int32 (auto-detected)
    const float* __restrict__ startT,      // [T]
    const float* __restrict__ endT,        // [T]
    const float* __restrict__ trans)       // [T,T]
{
    __shared__ __align__(16) float sP[4][2][TT];

    const unsigned FULL = 0xffffffffu;
    int tid = threadIdx.x;
    int w = tid >> 5;
    int l = tid & 31;
    int b = blockIdx.x * 4 + w;

    // ---- mask dtype detection + length (sum of monotone mask) ----
    // bool layout: byte (row1,col1)=1 almost surely; int32 layout: bytes at
    // offset %4 != 0 are always 0.
    bool isbool = ((mask[1] | mask[1025] | mask[2049] | mask[3073]) != 0);
    int cnt = 0;
    if (isbool) {
        const uchar4* m4 = reinterpret_cast<const uchar4*>(mask + (size_t)b * SS);
        #pragma unroll
        for (int k = 0; k < 8; k++) {
            uchar4 v = m4[l + 32 * k];
            cnt += v.x + v.y + v.z + v.w;
        }
    } else {
        const int* mi = reinterpret_cast<const int*>(mask) + (size_t)b * SS;
        #pragma unroll
        for (int k = 0; k < 32; k++) cnt += mi[l + 32 * k];
    }
    #pragma unroll
    for (int o = 16; o; o >>= 1) cnt += __shfl_xor_sync(FULL, cnt, o);
    int len = cnt;
    if (len < 1) len = 1;
    if (len > SS) len = SS;

    // ---- this lane's two output columns ----
    int jA = l;
    int jB = 32 + (l & 15);
    bool hasB = (l < 16);

    // ---- E = exp(transitions) columns in registers, packed as f32x2 pairs ----
    unsigned long long colA[24], colB[24];
    #pragma unroll
    for (int m = 0; m < 24; m++) {
        colA[m] = pk2(__expf(trans[(2 * m) * TT + jA]), __expf(trans[(2 * m + 1) * TT + jA]));
        colB[m] = pk2(__expf(trans[(2 * m) * TT + jB]), __expf(trans[(2 * m + 1) * TT + jB]));
    }

    const float* emb = em + (size_t)b * SS * TT;

    // ---- init: p0 = exp(start + emit0 - shift) ----
    float sA0 = startT[jA] + emb[jA];
    float sB0 = startT[jB] + emb[jB];
    float shift = __shfl_sync(FULL, sA0, 0);
    float pA = __expf(sA0 - shift);
    float pB = __expf(sB0 - shift);
    sP[w][0][l] = pA;
    if (hasB) sP[w][0][32 + l] = pB;
    __syncwarp();

    // ---- numerator state (lane 0 only) ----
    float num = 0.f;
    int tgp = 0, tg_cur = 0;
    if (l == 0) {
        tgp = tags[(size_t)b * SS];
        num = startT[tgp] + emb[tgp];
        tg_cur = tags[(size_t)b * SS + 1];   // tag for t=1 (unused if len==1)
    }

    // ---- rescale state ----
    float Mf = 1.0f;   // power-of-2 multiplier applied this step (lagged by 1)
    int kcur = 0;      // lane0: exponent count corresponding to Mf
    int ksum = 0;      // lane0: total applied exponent

    // ---- emission prefetch ring (depth 4) ----
    float bufA[4], bufB[4];
    #pragma unroll
    for (int u = 0; u < 4; u++) {
        int tp = 1 + u;
        bufA[u] = emb[tp * TT + jA];
        bufB[u] = emb[tp * TT + jB];
    }

    // ---- main recurrence: p <- (E^T p) * exp(emit_t) * M ----
    for (int t0 = 1; t0 < len; t0 += 4) {
        #pragma unroll
        for (int u = 0; u < 4; u++) {
            int t = t0 + u;
            if (t < len) {
                int rb = (t + 1) & 1;   // buffer holding p_{t-1}
                int wb = t & 1;

                // off-chain: w = exp(emit_t) (emission loaded 4 steps ago)
                float wA = __expf(bufA[u]);
                float wB = __expf(bufB[u]);

                // off-chain: numerator gathers for CURRENT tag, next-tag load
                float trv = 0.f, emv = 0.f;
                int tg_next = 0;
                if (l == 0) {
                    trv = trans[tgp * TT + tg_cur];
                    emv = emb[t * TT + tg_cur];
                    int tn = t + 1; if (tn > SS - 1) tn = SS - 1;
                    tg_next = tags[(size_t)b * SS + tn];
                }

                // prefetch emission row t+4
                int tp = t + 4; if (tp > SS - 1) tp = SS - 1;
                bufA[u] = emb[tp * TT + jA];
                bufB[u] = emb[tp * TT + jB];

                // matvec: acc_j = sum_i p[i] * E[i][j]   (12 LDS.128 + 48 FMA2)
                const ulonglong2* sp =
                    reinterpret_cast<const ulonglong2*>(&sP[w][rb][0]);
                unsigned long long a0 = 0, a1 = 0, c0 = 0, c1 = 0;
                #pragma unroll
                for (int q = 0; q < 12; q++) {
                    ulonglong2 pv = sp[q];
                    a0 = fma2(pv.x, colA[2 * q], a0);
                    a1 = fma2(pv.y, colA[2 * q + 1], a1);
                    c0 = fma2(pv.x, colB[2 * q], c0);
                    c1 = fma2(pv.y, colB[2 * q + 1], c1);
                }
                float xA, yA, xB, yB;
                upk2(add2(a0, a1), xA, yA);
                upk2(add2(c0, c1), xB, yB);
                pA = (xA + yA) * wA * Mf;
                pB = (xB + yB) * wB * Mf;

                // numerator accumulate + rescale bookkeeping (lane 0)
                if (l == 0) {
                    num += trv + emv;
                    tgp = tg_cur;
                    tg_cur = tg_next;
                    ksum += kcur;                        // k of Mf just applied
                    unsigned eb = (__float_as_uint(pA) >> 23) & 255u;
                    if (eb < 64u) eb = 64u;
                    if (eb > 190u) eb = 190u;
                    kcur = (int)eb - 127;                // next correction
                }
                float Mnew = __uint_as_float((unsigned)(127 - kcur) << 23); // 2^-kcur
                Mf = __shfl_sync(FULL, Mnew, 0);

                sP[w][wb][l] = pA;
                if (hasB) sP[w][wb][32 + l] = pB;
                __syncwarp();
            }
        }
    }

    // ---- finalize: logZ = log(sum_j p[j] * exp(end[j])) + shift + ksum*ln2 ----
    float fin = pA * __expf(endT[jA]);
    if (hasB) fin += pB * __expf(endT[jB]);
    #pragma unroll
    for (int o = 16; o; o >>= 1) fin += __shfl_xor_sync(FULL, fin, o);
    if (l == 0) {
        num += endT[tgp];
        float logZ = __logf(fin) + shift + (float)ksum * 0.69314718055994531f;
        g_partial[b] = logZ - num;
    }
}

__global__ void crf_reduce(float* __restrict__ out) {
    __shared__ float s[256];
    int tid = threadIdx.x;
    s[tid] = g_partial[tid] + g_partial[tid + 256];
    __syncthreads();
    #pragma unroll
    for (int o = 128; o > 0; o >>= 1) {
        if (tid < o) s[tid] += s[tid + o];
        __syncthreads();
    }
    if (tid == 0) out[0] = s[0] * (1.0f / (float)BB);
}

extern "C" void kernel_launch(void* const* d_in, const int* in_sizes, int n_in,
                              void* d_out, int out_size) {
    const float*         em   = (const float*)d_in[0];
    const int*           tags = (const int*)d_in[1];
    const unsigned char* mask = (const unsigned char*)d_in[2];
    const float*         st   = (const float*)d_in[3];
    const float*         en   = (const float*)d_in[4];
    const float*         tr   = (const float*)d_in[5];
    crf_main<<<BB / 4, 128>>>(em, tags, mask, st, en, tr);
    crf_reduce<<<1, 256>>>((float*)d_out);
}